// round 17
// baseline (speedup 1.0000x reference)
#include <cuda_runtime.h>
#include <cuda_fp16.h>
#include <math.h>

#define NBLK 128
#define NTHR 768
typedef unsigned int u32;

// activation tensors in fp16 A-fragment layout: tiles [bt][kt16][256 halves]
__device__ __align__(16) __half g_fcA[16*128*256];   // fc_in, K=2048
__device__ __align__(16) __half g_xA [16*32*256];    // map out, K=512
__device__ __align__(16) __half g_x1A[16*32*256];    // layer0 h2 (pre-tanh)
__device__ __align__(16) __half g_hA [4][16*32*256]; // tanh(h) [l*2+parity]
__device__ __align__(16) float  g_cT [2*512*256];    // c carry fp32, [l][b][j]
__device__ unsigned g_leaf[8*64];                    // 8 counters, 256B apart (monotonic)
__device__ unsigned g_root=0, g_gen=0;               // monotonic across launches

#define OFF_WMAP 0        // 64KB map W: [kt128][nt2][128 halves], 16 cols
#define OFF_WL0  65536    // 64KB lstm0: [kt64][nt4][128], 32 gate rows (8 units)
#define OFF_WL1  131072   // 64KB lstm1
#define OFF_BS   196608   // 80 floats
#define OFF_SC   197120   // scratch: gate tile 8*16*37*4 / map reduce 5*4*256*4 / init
#define SMEMSZ   217600

__device__ __forceinline__ int afx(int k, int b, int Kt16){
    return (((b>>4)*Kt16 + (k>>4))<<8) + (((b&7)*4 + ((k&7)>>1))<<3)
         + (((k>>3)&1)<<2) + (((b>>3)&1)<<1) + (k&1);
}
__device__ __forceinline__ float tanhap(float x){ float y; asm("tanh.approx.f32 %0,%1;":"=f"(y):"f"(x)); return y; }
__device__ __forceinline__ float sigm(float x){ return 0.5f + 0.5f*tanhap(0.5f*x); }

__device__ __forceinline__ void mma16(float* d, uint4 a, uint2 b){
    asm("mma.sync.aligned.m16n8k16.row.col.f32.f16.f16.f32 {%0,%1,%2,%3},{%4,%5,%6,%7},{%8,%9},{%0,%1,%2,%3};"
        : "+f"(d[0]),"+f"(d[1]),"+f"(d[2]),"+f"(d[3])
        : "r"(a.x),"r"(a.y),"r"(a.z),"r"(a.w),"r"(b.x),"r"(b.y));
}

// fully-unrolled pipelined GEMM over NG groups of 4 k-tiles, NTT n-tiles.
// A loads use __ldcg (L2-coherent, no L1) — cross-block data, no acquire fence needed.
template<int NG, int NTT>
__device__ __forceinline__ void gemm_t(const uint4* A, const __half* W, float* d){
    uint4 pa[2][4];
#pragma unroll
    for (int i=0;i<4;i++) pa[0][i] = __ldcg(A + i*32);
#pragma unroll
    for (int i=0;i<4;i++) pa[1][i] = (NG>1)? __ldcg(A + (4+i)*32) : pa[0][i];
#pragma unroll
    for (int g=0; g<NG; g++){
#pragma unroll
        for (int i=0;i<4;i++){
            const int kt = g*4+i;
#pragma unroll
            for (int nt=0; nt<NTT; nt++){
                uint2 w = *(const uint2*)(W + (kt*NTT+nt)*128);
                mma16(d+nt*4, pa[g&1][i], w);
            }
        }
        if (g+2 < NG){
#pragma unroll
            for (int i=0;i<4;i++) pa[g&1][i] = __ldcg(A + ((g+2)*4+i)*32);
        }
    }
}

// two-level grid barrier, replay-safe: epoch target is RELATIVE to gen0 snapshot
// taken at kernel entry (before this block's first arrival -> before any flip).
__device__ __forceinline__ void gbar(int& ep, unsigned gen0){
    __syncthreads();
    if (threadIdx.x == 0){
        __threadfence();   // release this block's global stores
        unsigned my = atomicAdd(&g_leaf[(blockIdx.x & 7)*64], 1u);
        if ((my & 15u) == 15u){
            unsigned r = atomicAdd(&g_root, 1u);
            if ((r & 7u) == 7u){
                __threadfence();
                atomicExch(&g_gen, (r >> 3) + 1u);
            }
        }
        const unsigned target = gen0 + (unsigned)ep + 1u;
        while (*(volatile unsigned*)&g_gen < target) __nanosleep(32);
        __threadfence();   // acquire (thread0 only; others order via bar.sync + ldcg)
    }
    __syncthreads();
    ep++;
}

// LSTM layer: block owns 8 units (32 gate rows = 4 n-tiles) x 128 batches.
// 24 warps = 8 bt x 3 k-splits over combined 64 kt (x:0..31, h:32..63), groups (6,5,5).
__device__ __forceinline__ void lstm_phase(int l, int p, const __half* xA, const __half* wS,
    const float* bsl, float* gt, int u0, int B0, int wt, int lane, int t)
{
    const int bt = wt & 7, ks = wt >> 3;
    const int btg = (B0>>4) + bt;
    float d[16];
#pragma unroll
    for (int i=0;i<16;i++) d[i]=0.f;
    const uint4* Ax = (const uint4*)(xA + (size_t)btg*32*256) + lane;
    const uint4* Ah = (const uint4*)(g_hA[l*2+p] + (size_t)btg*32*256) + lane;
    const __half* W = wS + lane*4;

    if (ks==0){
        gemm_t<6,4>(Ax, W, d);                         // x kt [0,24)
    } else if (ks==1){
        gemm_t<2,4>(Ax + 24*32, W + 24*4*128, d);      // x kt [24,32)
        gemm_t<3,4>(Ah,         W + 32*4*128, d);      // h kt [0,12)
    } else {
        gemm_t<5,4>(Ah + 12*32, W + 44*4*128, d);      // h kt [12,32)
    }

    float* gb = gt + bt*16*37;
    const int r1=lane>>2, c=2*(lane&3);
    if (ks==0){
#pragma unroll
        for (int nt=0;nt<4;nt++){
            gb[r1*37 + nt*8 + c]       = d[nt*4+0];
            gb[r1*37 + nt*8 + c+1]     = d[nt*4+1];
            gb[(r1+8)*37 + nt*8 + c]   = d[nt*4+2];
            gb[(r1+8)*37 + nt*8 + c+1] = d[nt*4+3];
        }
    }
    __syncthreads();
    if (ks==1){
#pragma unroll
        for (int nt=0;nt<4;nt++){
            gb[r1*37 + nt*8 + c]       += d[nt*4+0];
            gb[r1*37 + nt*8 + c+1]     += d[nt*4+1];
            gb[(r1+8)*37 + nt*8 + c]   += d[nt*4+2];
            gb[(r1+8)*37 + nt*8 + c+1] += d[nt*4+3];
        }
    }
    __syncthreads();
    if (ks==2){
#pragma unroll
        for (int nt=0;nt<4;nt++){
            gb[r1*37 + nt*8 + c]       += d[nt*4+0];
            gb[r1*37 + nt*8 + c+1]     += d[nt*4+1];
            gb[(r1+8)*37 + nt*8 + c]   += d[nt*4+2];
            gb[(r1+8)*37 + nt*8 + c+1] += d[nt*4+3];
        }
    }
    __syncthreads();
    // cell update: 512 pair-tasks (unit pair x 128 batches)
    if (t < 512){
        const int up = t>>7, bl = t&127;
        const int u = up*2, j = u0+u, b = B0+bl;
        const float* gr = gt + bl*37;
        float2 co = *(const float2*)(g_cT + (size_t)l*131072 + (size_t)b*512 + j);
        float thv[2], tcv[2], h2v[2];
#pragma unroll
        for (int i=0;i<2;i++){
            int uu = u+i;
            float gi=gr[uu]+bsl[uu], gf=gr[8+uu]+bsl[8+uu];
            float gg=gr[16+uu]+bsl[16+uu], go=gr[24+uu]+bsl[24+uu];
            float cold = i? co.y : co.x;
            float c2 = sigm(gf)*cold + sigm(gi)*tanhap(gg);
            float h2 = sigm(go)*tanhap(c2);
            h2v[i]=h2; thv[i]=tanhap(h2); tcv[i]=tanhap(c2);
        }
        *(float2*)(g_cT + (size_t)l*131072 + (size_t)b*512 + j) = make_float2(tcv[0],tcv[1]);
        *(__half2*)(g_hA[l*2+(p^1)] + afx(j,b,32)) = __floats2half2_rn(thv[0],thv[1]);
        if (l==0) *(__half2*)(g_x1A + afx(j,b,32)) = __floats2half2_rn(h2v[0],h2v[1]);
        int rf=l*128+(b>>1), ch=(b&1)*1024+j;
        *(__half2*)(g_fcA + afx(ch,rf,128))     = __floats2half2_rn(thv[0],thv[1]);
        *(__half2*)(g_fcA + afx(ch+512,rf,128)) = __floats2half2_rn(tcv[0],tcv[1]);
    }
}

extern "C" __global__ void __launch_bounds__(NTHR,1)
dec_kernel(const float* __restrict__ latent, const float* __restrict__ fc_w,
    const float* __restrict__ fc_b, const float* __restrict__ map_w, const float* __restrict__ map_b,
    const float* __restrict__ wih0, const float* __restrict__ whh0, const float* __restrict__ bih0,
    const float* __restrict__ bhh0, const float* __restrict__ wih1, const float* __restrict__ whh1,
    const float* __restrict__ bih1, const float* __restrict__ bhh1, float* __restrict__ out)
{
    extern __shared__ unsigned char smem[];
    __half* wmapS=(__half*)(smem+OFF_WMAP);
    __half* w0S  =(__half*)(smem+OFF_WL0);
    __half* w1S  =(__half*)(smem+OFF_WL1);
    float*  bs   =(float*) (smem+OFF_BS);
    float*  sc   =(float*) (smem+OFF_SC);
    const int t=threadIdx.x, blk=blockIdx.x;
    const int wt=t>>5, lane=t&31;
    const int u0=(blk>>1)*8, B0=(blk&1)*128;         // lstm: 8 units x 128 batches
    const int j0m=(blk>>2)*16, B0m=(blk&3)*64;       // map: 16 cols x 64 batches
    int ep = 0;
    unsigned gen0 = 0;
    if (t == 0) gen0 = *(volatile unsigned*)&g_gen;   // replay-safe epoch base

    // ---- weights -> smem, B-frag half layout ----
    for (int idx=t; idx<32768; idx+=NTHR){           // map: [kt128][nt2][128]
        int kt=idx>>8, rem=idx&255, nt=rem>>7, r2=rem&127, ln=r2>>2, q2=r2&3, sl=q2>>1, klo=q2&1;
        int nr=ln>>2, tn=ln&3;
        int col=j0m + nt*8 + nr, k=kt*16 + sl*8 + tn*2 + klo;
        wmapS[idx]=__float2half(map_w[(size_t)col*2048 + k]);
    }
    for (int idx=t; idx<32768; idx+=NTHR){           // lstm: [kt64][nt4][128]
        int kt=idx>>9, rem=idx&511, nt=rem>>7, r2=rem&127, ln=r2>>2, q2=r2&3, sl=q2>>1, klo=q2&1;
        int nr=ln>>2, tn=ln&3;
        int rr=nt*8+nr, k=kt*16 + sl*8 + tn*2 + klo;
        int row=(rr>>3)*512 + u0 + (rr&7);
        w0S[idx]=__float2half(k<512? wih0[(size_t)row*512+k] : whh0[(size_t)row*512+k-512]);
        w1S[idx]=__float2half(k<512? wih1[(size_t)row*512+k] : whh1[(size_t)row*512+k-512]);
    }
    if (t<32){ int row=(t>>3)*512 + u0 + (t&7); bs[t]=bih0[row]+bhh0[row]; bs[32+t]=bih1[row]+bhh1[row]; }
    if (t<16) bs[64+t]=map_b[j0m+t];
    __syncthreads();

    // ---- init: dec = tanh(latent @ fc_w.T + fc_b), scatter to frag tensors ----
    {
        float* sL=sc;  int b0=blk*2;
        for (int idx=t; idx<512; idx+=NTHR)
            sL[idx]=latent[(size_t)(b0+(idx>>8))*256 + (idx&255)];
        __syncthreads();
        if (t < 512){
            int bi = t>>8, jb = (t&255)*8, b = b0+bi;
            const float* la = sL+bi*256;
            for (int m=0;m<8;m++){
                int jj=jb+m; float s=fc_b[jj];
                const float4* wr=(const float4*)(fc_w+(size_t)jj*256);
#pragma unroll 4
                for (int k4=0;k4<64;k4++){
                    float4 w=wr[k4];
                    s += la[k4*4]*w.x + la[k4*4+1]*w.y + la[k4*4+2]*w.z + la[k4*4+3]*w.w;
                }
                float val=tanhf(s);
                int l=b>>7, b2=((b&127)*2 + (jj>>10)), jj2=jj&1023;
                if (jj2<512) g_hA[l*2][afx(jj2,b2,32)]=__float2half(val);
                else         g_cT[(size_t)l*131072 + (size_t)b2*512 + (jj2-512)]=val;
                int rf=l*128+(b2>>1), ch=(b2&1)*1024+jj2;
                g_fcA[afx(ch,rf,128)]=__float2half(val);
            }
        }
        __syncthreads();
    }
    gbar(ep, gen0);

    // ================= 256 sequential steps =================
    for (int step=0; step<256; step++){
        int p=step&1;
        // ---- map: 16 cols x 64 batches; warp = (bt 0..3, ks 0..5); K=2048 split 6-way ----
        {
            const int btm = wt & 3, ksm = wt >> 2;
            const int btg = (B0m>>4) + btm;
            float d[8]={0,0,0,0,0,0,0,0};
            const uint4* A=(const uint4*)(g_fcA + (size_t)btg*128*256)+lane;
            const __half* W=wmapS + lane*4;
            switch (ksm){
                case 0: gemm_t<6,2>(A,         W,            d); break;
                case 1: gemm_t<6,2>(A+ 24*32,  W+ 24*2*128,  d); break;
                case 2: gemm_t<5,2>(A+ 48*32,  W+ 48*2*128,  d); break;
                case 3: gemm_t<5,2>(A+ 68*32,  W+ 68*2*128,  d); break;
                case 4: gemm_t<5,2>(A+ 88*32,  W+ 88*2*128,  d); break;
                default:gemm_t<5,2>(A+108*32,  W+108*2*128,  d); break;
            }
            if (ksm){
                float4* dst=(float4*)(sc + ((ksm-1)*4 + btm)*256 + lane*8);
                dst[0]=make_float4(d[0],d[1],d[2],d[3]);
                dst[1]=make_float4(d[4],d[5],d[6],d[7]);
            }
            __syncthreads();
            if (!ksm){
#pragma unroll
                for (int g=0;g<5;g++){
                    const float4* src=(const float4*)(sc + (g*4 + btm)*256 + lane*8);
                    float4 q0=src[0], q1=src[1];
                    d[0]+=q0.x; d[1]+=q0.y; d[2]+=q0.z; d[3]+=q0.w;
                    d[4]+=q1.x; d[5]+=q1.y; d[6]+=q1.z; d[7]+=q1.w;
                }
                int r1=lane>>2, c=2*(lane&3);
                int b1 = B0m + btm*16 + r1, b2 = b1+8;
#pragma unroll
                for (int nt=0;nt<2;nt++){
                    int col = j0m + nt*8 + c;
                    float o0=sigm(d[nt*4+0]+bs[64+nt*8+c]), o1=sigm(d[nt*4+1]+bs[64+nt*8+c+1]);
                    float o2=sigm(d[nt*4+2]+bs[64+nt*8+c]), o3=sigm(d[nt*4+3]+bs[64+nt*8+c+1]);
                    *(float2*)(out + ((size_t)step*256+b1)*512 + col) = make_float2(o0,o1);
                    *(float2*)(out + ((size_t)step*256+b2)*512 + col) = make_float2(o2,o3);
                    *(__half2*)(g_xA + afx(col, b1, 32)) = __floats2half2_rn(o0,o1);
                    *(__half2*)(g_xA + afx(col, b2, 32)) = __floats2half2_rn(o2,o3);
                }
            }
        }
        gbar(ep, gen0);
        lstm_phase(0,p,g_xA,  w0S, bs,    sc, u0, B0, wt, lane, t);
        gbar(ep, gen0);
        lstm_phase(1,p,g_x1A, w1S, bs+32, sc, u0, B0, wt, lane, t);
        gbar(ep, gen0);
    }
}

extern "C" void kernel_launch(void* const* d_in, const int* in_sizes, int n_in,
                              void* d_out, int out_size)
{
    cudaFuncSetAttribute(dec_kernel, cudaFuncAttributeMaxDynamicSharedMemorySize, SMEMSZ);
    dec_kernel<<<NBLK, NTHR, SMEMSZ>>>(
        (const float*)d_in[0], (const float*)d_in[1], (const float*)d_in[2],
        (const float*)d_in[3], (const float*)d_in[4], (const float*)d_in[5],
        (const float*)d_in[6], (const float*)d_in[7], (const float*)d_in[8],
        (const float*)d_in[9], (const float*)d_in[10], (const float*)d_in[11],
        (const float*)d_in[12], (float*)d_out);
}